// round 17
// baseline (speedup 1.0000x reference)
#include <cuda_runtime.h>
#include <cuda_bf16.h>
#include <cuda_fp16.h>
#include <mma.h>

using namespace nvcuda;

#define NMAX 50000
#define EMAX 800000
#define GRAPHS 64
#define SCAN_B 1024

// ---------------- device scratch (allocation-free rule) ----------------
static __device__ __half g_h0[NMAX * 64];   // layer-1 output, fp16
static __device__ __half g_h1[NMAX * 128];  // layer-2 output, fp16
// W2/W3 in fp16, TILE-CONTIGUOUS layout: tile (kt, ct) of 16x16 stored
// row-major at offset (kt*8 + ct)*256. Fragment loads become 512B contiguous.
static __device__ __half g_w2t[64 * 128];
static __device__ __half g_w3t[128 * 128];
static __device__ float4 g_x4[NMAX];        // x padded to float4
static __device__ float g_dinv[NMAX];
static __device__ int   g_cnt[NMAX];
static __device__ int   g_rowptr[NMAX + 1];
static __device__ int   g_cursor[NMAX];
static __device__ int   g_bsum[64];
static __device__ int   g_sync;             // zero-init at load; self-reset per launch
static __device__ unsigned long long g_edge[EMAX];  // packed {norm<<32 | src}
static __device__ float g_psum[GRAPHS * 128];
static __device__ float g_pcnt[GRAPHS];

typedef unsigned long long ull;

__device__ __forceinline__ void eunpack(ull r, int& s, float& w) {
    s = (int)(unsigned)r;
    w = __uint_as_float((unsigned)(r >> 32));
}

// spin grid barrier helper
__device__ __forceinline__ void grid_bar(int t, int target) {
    __threadfence();
    __syncthreads();
    if (t == 0) {
        atomicAdd(&g_sync, 1);
        while (atomicAdd(&g_sync, 0) < target) { }
    }
    __syncthreads();
}

// Single-wave prep: zero/convert/tile-W -> count -> scan -> fill.
__global__ void __launch_bounds__(1024) k_prep(const int* __restrict__ src,
                                               const int* __restrict__ dst,
                                               const int* __restrict__ batch,
                                               const float* __restrict__ W2,
                                               const float* __restrict__ W3,
                                               const float* __restrict__ x,
                                               int n, int E) {
    __shared__ int swarp[32];
    __shared__ int pref[64];
    __shared__ int wtot;
    int t = threadIdx.x;
    int lane = t & 31, wid = t >> 5;
    int nb = gridDim.x;
    int gtid = blockIdx.x * SCAN_B + t;
    int nthr = nb * SCAN_B;

    // ---- phase 0: zero + fp16 W tiling + x padding ----
    for (int i = gtid; i < n; i += nthr) {
        g_cnt[i] = 0;
        g_x4[i] = make_float4(x[i * 3], x[i * 3 + 1], x[i * 3 + 2], 0.0f);
    }
    if (gtid < GRAPHS * 128) g_psum[gtid] = 0.0f;
    if (gtid < GRAPHS) g_pcnt[gtid] = 0.0f;
    if (gtid < 64 * 128) {
        int k = gtid >> 7, c = gtid & 127;
        int d = ((k >> 4) * 8 + (c >> 4)) * 256 + (k & 15) * 16 + (c & 15);
        g_w2t[d] = __float2half(W2[gtid]);
    }
    if (gtid < 128 * 128) {
        int k = gtid >> 7, c = gtid & 127;
        int d = ((k >> 4) * 8 + (c >> 4)) * 256 + (k & 15) * 16 + (c & 15);
        g_w3t[d] = __float2half(W3[gtid]);
    }
    grid_bar(t, nb);

    // ---- phase 1: histograms ----
    for (int e = gtid; e < E; e += nthr) atomicAdd(&g_cnt[dst[e]], 1);
    for (int i = gtid; i < n; i += nthr) atomicAdd(&g_pcnt[batch[i]], 1.0f);
    grid_bar(t, 2 * nb);

    // ---- phase 2: local scan + dinv ----
    int i = gtid;
    int v = (i < n) ? g_cnt[i] : 0;
    if (i < n) g_dinv[i] = rsqrtf((float)v + 1.0f);
    int incl = v;
#pragma unroll
    for (int off = 1; off < 32; off <<= 1) {
        int y = __shfl_up_sync(0xffffffffu, incl, off);
        if (lane >= off) incl += y;
    }
    if (lane == 31) swarp[wid] = incl;
    __syncthreads();
    if (wid == 0) {
        int w = swarp[lane];
#pragma unroll
        for (int off = 1; off < 32; off <<= 1) {
            int y = __shfl_up_sync(0xffffffffu, w, off);
            if (lane >= off) w += y;
        }
        swarp[lane] = w;
    }
    __syncthreads();
    int excl = incl - v + ((wid > 0) ? swarp[wid - 1] : 0);
    if (t == SCAN_B - 1) g_bsum[blockIdx.x] = excl + v;
    grid_bar(t, 3 * nb);

    // ---- phase 3: prefix block totals, write rowptr/cursor ----
    if (t < 64) {
        int bv = (t < nb) ? g_bsum[t] : 0;
        int binc = bv;
#pragma unroll
        for (int off = 1; off < 32; off <<= 1) {
            int y = __shfl_up_sync(0xffffffffu, binc, off);
            if (lane >= off) binc += y;
        }
        pref[t] = binc - bv;
        if (t == 31) wtot = binc;
    }
    __syncthreads();
    if (t >= 32 && t < 64) pref[t] += wtot;
    __syncthreads();
    if (i < n) {
        int rp = excl + pref[blockIdx.x];
        g_rowptr[i] = rp;
        g_cursor[i] = rp;
    }
    if (gtid == 0) g_rowptr[n] = E;
    grid_bar(t, 4 * nb);

    // ---- phase 4: fill packed edge records ----
    for (int e = gtid; e < E; e += nthr) {
        int s = src[e], d = dst[e];
        int pos = atomicAdd(&g_cursor[d], 1);
        float nm = g_dinv[s] * g_dinv[d];
        g_edge[pos] = ((ull)__float_as_uint(nm) << 32) | (unsigned)s;
    }

    // ---- final: self-reset g_sync ----
    __threadfence();
    __syncthreads();
    if (t == 0) {
        int tk = atomicAdd(&g_sync, 1);
        if (tk == 5 * nb - 1) g_sync = 0;
    }
}

// ---------------- Layer 1 fused: agg(C=3) + 3->64 GEMM + relu -> g_h0 -------
__global__ void __launch_bounds__(256) k_layer1(const float* __restrict__ W,
                                                const float* __restrict__ b, int n) {
    const int NPB = 64;
    __shared__ float sa[NPB][3];
    __shared__ float sW[192];
    __shared__ float sb[64];
    int tid = threadIdx.x, wid = tid >> 5, lane = tid & 31;
    int node0 = blockIdx.x * NPB;
    if (tid < 192) sW[tid] = W[tid];
    if (tid < 64) sb[tid] = b[tid];

    for (int k = 0; k < NPB; k += 8) {
        int lr = k + wid;
        int i = node0 + lr;
        if (i < n) {
            int beg = g_rowptr[i], end = g_rowptr[i + 1];
            float a0 = 0.f, a1 = 0.f, a2 = 0.f;
            for (int j = beg + lane; j < end; j += 32) {
                int s; float w; eunpack(g_edge[j], s, w);
                float4 xv = g_x4[s];
                a0 += xv.x * w;
                a1 += xv.y * w;
                a2 += xv.z * w;
            }
#pragma unroll
            for (int off = 16; off > 0; off >>= 1) {
                a0 += __shfl_down_sync(0xffffffffu, a0, off);
                a1 += __shfl_down_sync(0xffffffffu, a1, off);
                a2 += __shfl_down_sync(0xffffffffu, a2, off);
            }
            if (lane == 0) {
                float di = g_dinv[i], sw = di * di;
                float4 xv = g_x4[i];
                sa[lr][0] = a0 + xv.x * sw;
                sa[lr][1] = a1 + xv.y * sw;
                sa[lr][2] = a2 + xv.z * sw;
            }
        }
    }
    __syncthreads();

    int tc = tid & 63, ty = tid >> 6;
    float w0 = sW[tc], w1 = sW[64 + tc], w2 = sW[128 + tc], bb = sb[tc];
#pragma unroll 4
    for (int r = 0; r < 16; r++) {
        int lr = ty * 16 + r;
        int row = node0 + lr;
        if (row >= n) break;
        float v = bb + sa[lr][0] * w0 + sa[lr][1] * w1 + sa[lr][2] * w2;
        g_h0[row * 64 + tc] = __float2half(fmaxf(v, 0.0f));
    }
}

// ---------------- Fused layer: agg(K) + KxC GEMM via WMMA (+relu) ----------
// K in {64,128}, C=128. Block: 256 thr, ROWS nodes.
// Phase A: warp aggregates ROWS/8 nodes (fp32 accum), stores fp16 to shA.
// Phase B: fb from tile-contiguous global W; fa fragment REUSED across row
// tiles; fc accumulators held in regs across the barrier, then sC OVERWRITES
// the shA buffer (union) -> smem 8.4/16.9KB; launch_bounds(256,8) -> 8 blk/SM.
template <int K, int VPL, int ROWS, bool POOL>
__global__ void __launch_bounds__(256, 8) k_layer(const float* __restrict__ b,
                                                  const int* __restrict__ batch, int n) {
    const int C = 128;
    const int Kp = K + 8;      // half elems; row stride mult of 16B
    const int Cp4 = 132;       // float elems; 528B row stride
    const int NPW = ROWS / 8;  // nodes per warp in phase A
    const int RT = ROWS / 16;  // row tiles in phase B
    const int RPE = ROWS / 4;  // rows per ty group in epilogue
    const int BUFB = (ROWS * Kp * 2 > ROWS * Cp4 * 4) ? ROWS * Kp * 2 : ROWS * Cp4 * 4;
    __shared__ __align__(16) char sbuf[BUFB];
    __half* shA = (__half*)sbuf;
    float* sC = (float*)sbuf;

    int tid = threadIdx.x, wid = tid >> 5, lane = tid & 31;
    int row0 = blockIdx.x * ROWS;
    const __half* __restrict__ hp = (K == 64) ? g_h0 : g_h1;
    const __half* __restrict__ Wt = (K == 64) ? g_w2t : g_w3t;

    // ---- phase A: aggregation ----
#pragma unroll
    for (int rr = 0; rr < NPW; rr++) {
        int lr = wid * NPW + rr;
        int i = row0 + lr;
        if (i < n) {
            int beg = g_rowptr[i], end = g_rowptr[i + 1];
            float di = g_dinv[i], sw = di * di;
            float acc[VPL];
            if (VPL == 4) {
                uint2 u = *(const uint2*)(hp + (size_t)i * K + lane * 4);
                float2 f0 = __half22float2(*reinterpret_cast<__half2*>(&u.x));
                float2 f1 = __half22float2(*reinterpret_cast<__half2*>(&u.y));
                acc[0] = f0.x * sw; acc[1] = f0.y * sw; acc[2] = f1.x * sw; acc[3] = f1.y * sw;
            } else {
                unsigned u = *(const unsigned*)(hp + (size_t)i * K + lane * 2);
                float2 f0 = __half22float2(*reinterpret_cast<__half2*>(&u));
                acc[0] = f0.x * sw; acc[1] = f0.y * sw;
            }
            int j = beg;
            for (; j + 4 <= end; j += 4) {
                int s0, s1, s2, s3; float w0, w1, w2, w3;
                eunpack(g_edge[j], s0, w0);
                eunpack(g_edge[j + 1], s1, w1);
                eunpack(g_edge[j + 2], s2, w2);
                eunpack(g_edge[j + 3], s3, w3);
                if (VPL == 4) {
                    uint2 u0 = *(const uint2*)(hp + (size_t)s0 * K + lane * 4);
                    uint2 u1 = *(const uint2*)(hp + (size_t)s1 * K + lane * 4);
                    uint2 u2 = *(const uint2*)(hp + (size_t)s2 * K + lane * 4);
                    uint2 u3 = *(const uint2*)(hp + (size_t)s3 * K + lane * 4);
                    float2 a0 = __half22float2(*reinterpret_cast<__half2*>(&u0.x));
                    float2 b0 = __half22float2(*reinterpret_cast<__half2*>(&u0.y));
                    float2 a1 = __half22float2(*reinterpret_cast<__half2*>(&u1.x));
                    float2 b1 = __half22float2(*reinterpret_cast<__half2*>(&u1.y));
                    float2 a2 = __half22float2(*reinterpret_cast<__half2*>(&u2.x));
                    float2 b2 = __half22float2(*reinterpret_cast<__half2*>(&u2.y));
                    float2 a3 = __half22float2(*reinterpret_cast<__half2*>(&u3.x));
                    float2 b3 = __half22float2(*reinterpret_cast<__half2*>(&u3.y));
                    acc[0] += a0.x * w0 + a1.x * w1 + a2.x * w2 + a3.x * w3;
                    acc[1] += a0.y * w0 + a1.y * w1 + a2.y * w2 + a3.y * w3;
                    acc[2] += b0.x * w0 + b1.x * w1 + b2.x * w2 + b3.x * w3;
                    acc[3] += b0.y * w0 + b1.y * w1 + b2.y * w2 + b3.y * w3;
                } else {
                    unsigned u0 = *(const unsigned*)(hp + (size_t)s0 * K + lane * 2);
                    unsigned u1 = *(const unsigned*)(hp + (size_t)s1 * K + lane * 2);
                    unsigned u2 = *(const unsigned*)(hp + (size_t)s2 * K + lane * 2);
                    unsigned u3 = *(const unsigned*)(hp + (size_t)s3 * K + lane * 2);
                    float2 a0 = __half22float2(*reinterpret_cast<__half2*>(&u0));
                    float2 a1 = __half22float2(*reinterpret_cast<__half2*>(&u1));
                    float2 a2 = __half22float2(*reinterpret_cast<__half2*>(&u2));
                    float2 a3 = __half22float2(*reinterpret_cast<__half2*>(&u3));
                    acc[0] += a0.x * w0 + a1.x * w1 + a2.x * w2 + a3.x * w3;
                    acc[1] += a0.y * w0 + a1.y * w1 + a2.y * w2 + a3.y * w3;
                }
            }
            for (; j < end; j++) {
                int s; float w; eunpack(g_edge[j], s, w);
                if (VPL == 4) {
                    uint2 u = *(const uint2*)(hp + (size_t)s * K + lane * 4);
                    float2 f0 = __half22float2(*reinterpret_cast<__half2*>(&u.x));
                    float2 f1 = __half22float2(*reinterpret_cast<__half2*>(&u.y));
                    acc[0] += f0.x * w; acc[1] += f0.y * w; acc[2] += f1.x * w; acc[3] += f1.y * w;
                } else {
                    unsigned u = *(const unsigned*)(hp + (size_t)s * K + lane * 2);
                    float2 f0 = __half22float2(*reinterpret_cast<__half2*>(&u));
                    acc[0] += f0.x * w; acc[1] += f0.y * w;
                }
            }
#pragma unroll
            for (int v = 0; v < VPL; v += 2) {
                __half2 hh = __floats2half2_rn(acc[v], acc[v + 1]);
                *(__half2*)&shA[lr * Kp + lane * VPL + v] = hh;
            }
        } else {
#pragma unroll
            for (int v = 0; v < VPL; v += 2)
                *(__half2*)&shA[lr * Kp + lane * VPL + v] = __floats2half2_rn(0.f, 0.f);
        }
    }
    __syncthreads();

    // ---- phase B: WMMA; fa reused across row tiles, fb from global W ----
    {
        wmma::fragment<wmma::matrix_a, 16, 16, 16, __half, wmma::row_major> fa;
        wmma::fragment<wmma::matrix_b, 16, 16, 16, __half, wmma::row_major> fb;
        wmma::fragment<wmma::accumulator, 16, 16, 16, float> fc[RT];
#pragma unroll
        for (int rt = 0; rt < RT; rt++) wmma::fill_fragment(fc[rt], 0.0f);
#pragma unroll
        for (int k = 0; k < K; k += 16) {
            wmma::load_matrix_sync(fb, Wt + ((k >> 4) * 8 + wid) * 256, 16);
#pragma unroll
            for (int rt = 0; rt < RT; rt++) {
                wmma::load_matrix_sync(fa, shA + rt * 16 * Kp + k, Kp);
                wmma::mma_sync(fc[rt], fa, fb, fc[rt]);
            }
        }
        __syncthreads();  // everyone done reading shA; sC may overwrite it
#pragma unroll
        for (int rt = 0; rt < RT; rt++)
            wmma::store_matrix_sync(sC + rt * 16 * Cp4 + wid * 16, fc[rt], Cp4,
                                    wmma::mem_row_major);
    }
    __syncthreads();

    // ---- epilogue: bias + relu (+ pool) from sC ----
    int tc = tid & 63, ty = tid >> 6;
    float2 bb = *(const float2*)&b[2 * tc];
    if (!POOL) {
#pragma unroll
        for (int r = 0; r < RPE; r++) {
            int lr = ty * RPE + r;
            int row = row0 + lr;
            if (row < n) {
                float xv = sC[lr * Cp4 + 2 * tc] + bb.x;
                float yv = sC[lr * Cp4 + 2 * tc + 1] + bb.y;
                __half2 o = __floats2half2_rn(fmaxf(xv, 0.0f), fmaxf(yv, 0.0f));
                *(__half2*)&g_h1[(size_t)row * C + 2 * tc] = o;
            }
        }
    } else {
        int curg = -1;
        float rx = 0.0f, ry = 0.0f;
#pragma unroll
        for (int r = 0; r < RPE; r++) {
            int lr = ty * RPE + r;
            int row = row0 + lr;
            if (row >= n) break;
            float xv = fmaxf(sC[lr * Cp4 + 2 * tc] + bb.x, 0.0f);
            float yv = fmaxf(sC[lr * Cp4 + 2 * tc + 1] + bb.y, 0.0f);
            int g = __ldg(&batch[row]);
            if (g != curg) {
                if (curg >= 0) {
                    atomicAdd(&g_psum[curg * 128 + 2 * tc], rx);
                    atomicAdd(&g_psum[curg * 128 + 2 * tc + 1], ry);
                }
                curg = g; rx = 0.0f; ry = 0.0f;
            }
            rx += xv; ry += yv;
        }
        if (curg >= 0) {
            atomicAdd(&g_psum[curg * 128 + 2 * tc], rx);
            atomicAdd(&g_psum[curg * 128 + 2 * tc + 1], ry);
        }
    }
}

// ---------------- MLP head ----------------
__global__ void k_fc(const float* __restrict__ Wf1, const float* __restrict__ bf1,
                     const float* __restrict__ Wf2, const float* __restrict__ bf2,
                     float* __restrict__ out) {
    int g = blockIdx.x;
    int t = threadIdx.x;  // 128
    __shared__ float p[128];
    __shared__ float f1[64];
    float inv = 1.0f / fmaxf(g_pcnt[g], 1.0f);
    p[t] = g_psum[g * 128 + t] * inv;
    __syncthreads();
    if (t < 64) {
        float acc = bf1[t];
#pragma unroll
        for (int k = 0; k < 128; k++) acc += p[k] * Wf1[k * 64 + t];
        f1[t] = fmaxf(acc, 0.0f);
    }
    __syncthreads();
    if (t < 10) {
        float acc = bf2[t];
#pragma unroll
        for (int k = 0; k < 64; k++) acc += f1[k] * Wf2[k * 10 + t];
        out[g * 10 + t] = acc;
    }
}

extern "C" void kernel_launch(void* const* d_in, const int* in_sizes, int n_in,
                              void* d_out, int out_size) {
    const float* x   = (const float*)d_in[0];
    const int* ei    = (const int*)d_in[1];
    const int* batch = (const int*)d_in[2];
    const float* W1  = (const float*)d_in[3];
    const float* b1  = (const float*)d_in[4];
    const float* W2  = (const float*)d_in[5];
    const float* b2  = (const float*)d_in[6];
    const float* W3  = (const float*)d_in[7];
    const float* b3  = (const float*)d_in[8];
    const float* Wf1 = (const float*)d_in[9];
    const float* bf1 = (const float*)d_in[10];
    const float* Wf2 = (const float*)d_in[11];
    const float* bf2 = (const float*)d_in[12];
    float* out = (float*)d_out;

    int N = in_sizes[0] / 3;
    int E = in_sizes[1] / 2;
    const int* src = ei;
    const int* dst = ei + E;
    int NB = (N + SCAN_B - 1) / SCAN_B;  // <= 49

    // single-wave prep (zero + W tiling + CSR build)
    k_prep<<<NB, SCAN_B>>>(src, dst, batch, W2, W3, x, N, E);

    // Fused layers (per-K measured-optimal tile sizes)
    k_layer1<<<(N + 63) / 64, 256>>>(W1, b1, N);
    k_layer<64, 2, 16, false><<<(N + 15) / 16, 256>>>(b2, batch, N);
    k_layer<128, 4, 32, true><<<(N + 31) / 32, 256>>>(b3, batch, N);

    // Head
    k_fc<<<GRAPHS, 128>>>(Wf1, bf1, Wf2, bf2, out);
}